// round 8
// baseline (speedup 1.0000x reference)
#include <cuda_runtime.h>
#include <cuda_bf16.h>
#include <cstdint>

#define H 128
#define NB 8
#define NV 1024
#define NM 64

// ---------------------------------------------------------------------------
// Scratch (device globals — no allocation allowed)
// ---------------------------------------------------------------------------
__device__ float g_WeffV[H * H];
__device__ float g_beffV[H];
__device__ float g_WeffL[H * H];
__device__ float g_beffL[H];
__device__ float g_vp[NB * NV * H];     // v_part (folded)  [8192,128]
__device__ float g_lb[NB * NM * H];     // l_part + b1      [512,128]
__device__ uint32_t g_W2hi[64 * 64];    // W2 bf16-hi, word[kp][j] (kp = k/2)
__device__ uint32_t g_W2lo[64 * 64];    // W2 bf16-lo residual
__device__ float g_z[NB * NM * NV];     // pairwise logits [512,1024]

// ---------------------------------------------------------------------------
// Helpers
// ---------------------------------------------------------------------------
__device__ __forceinline__ uint32_t pack_bf16(__nv_bfloat16 lo_elem, __nv_bfloat16 hi_elem) {
    return (uint32_t)__bfloat16_as_ushort(lo_elem) |
           ((uint32_t)__bfloat16_as_ushort(hi_elem) << 16);
}

__device__ __forceinline__ void bf16_split(float x, __nv_bfloat16& hi, __nv_bfloat16& lo) {
    hi = __float2bfloat16(x);
    lo = __float2bfloat16(x - __bfloat162float(hi));
}

// bf16 tensor-core MMA (sm_80+ baseline PTX): D[16x8] += A[16x16]*B[16x8], f32 accum.
__device__ __forceinline__ void mma_bf16(float c[4], const uint32_t a[4], const uint32_t b[2]) {
    asm volatile(
        "mma.sync.aligned.m16n8k16.row.col.f32.bf16.bf16.f32 "
        "{%0,%1,%2,%3}, {%4,%5,%6,%7}, {%8,%9}, {%0,%1,%2,%3};"
        : "+f"(c[0]), "+f"(c[1]), "+f"(c[2]), "+f"(c[3])
        : "r"(a[0]), "r"(a[1]), "r"(a[2]), "r"(a[3]), "r"(b[0]), "r"(b[1]));
}

// ---------------------------------------------------------------------------
// Kernel 1: fold Wv@W1[H:] and Wl@W1[:H] (+ biases) into single 128x128 mats.
// ---------------------------------------------------------------------------
__global__ void fold_kernel(const float* __restrict__ Wv, const float* __restrict__ bv,
                            const float* __restrict__ Wl, const float* __restrict__ bl,
                            const float* __restrict__ W1, const float* __restrict__ b1)
{
    int h = threadIdx.x;
    int row = blockIdx.x;      // 0..128
    int which = blockIdx.y;    // 0 = virtual, 1 = ligand
    const float* A;
    int w1off;
    if (which == 0) { A = (row < H) ? (Wv + row * H) : bv; w1off = H; }
    else            { A = (row < H) ? (Wl + row * H) : bl; w1off = 0; }
    float a0 = 0.f, a1 = 0.f, a2 = 0.f, a3 = 0.f;
#pragma unroll 8
    for (int hid = 0; hid < H; hid += 4) {
        a0 += A[hid + 0] * W1[(w1off + hid + 0) * H + h];
        a1 += A[hid + 1] * W1[(w1off + hid + 1) * H + h];
        a2 += A[hid + 2] * W1[(w1off + hid + 2) * H + h];
        a3 += A[hid + 3] * W1[(w1off + hid + 3) * H + h];
    }
    float acc = (a0 + a1) + (a2 + a3);
    if (row < H) {
        (which == 0 ? g_WeffV : g_WeffL)[row * H + h] = acc;
    } else {
        if (which == 1) acc += b1[h];
        (which == 0 ? g_beffV : g_beffL)[h] = acc;
    }
}

// ---------------------------------------------------------------------------
// Kernel 1b: split W2 into bf16 hi/lo planes, word layout [kp][j], kp=k/2.
// ---------------------------------------------------------------------------
__global__ void w2split_kernel(const float* __restrict__ W2)
{
    int kp = blockIdx.x, j = threadIdx.x;
    float w0 = W2[(2 * kp) * 64 + j];
    float w1 = W2[(2 * kp + 1) * 64 + j];
    __nv_bfloat16 h0, l0, h1, l1;
    bf16_split(w0, h0, l0);
    bf16_split(w1, h1, l1);
    g_W2hi[kp * 64 + j] = pack_bf16(h0, h1);
    g_W2lo[kp * 64 + j] = pack_bf16(l0, l1);
}

// ---------------------------------------------------------------------------
// Kernel 2: projections (known-good from R2).
// ---------------------------------------------------------------------------
__global__ void proj_kernel(const float* __restrict__ virt, const float* __restrict__ lig)
{
    extern __shared__ float sm[];
    float* Ws = sm;
    float* As = Ws + H * H;
    float* bs = As + 32 * H;

    int bid = blockIdx.x;
    const float *A, *W, *bias;
    float* C;
    if (bid < 256) { A = virt + bid * 32 * H; W = g_WeffV; bias = g_beffV; C = g_vp + bid * 32 * H; }
    else { int r = bid - 256; A = lig + r * 32 * H; W = g_WeffL; bias = g_beffL; C = g_lb + r * 32 * H; }

    int tid = threadIdx.x;
    for (int i = tid; i < H * H / 4; i += 256)
        ((float4*)Ws)[i] = ((const float4*)W)[i];
    for (int i = tid; i < 32 * H / 4; i += 256)
        ((float4*)As)[i] = ((const float4*)A)[i];
    if (tid < H) bs[tid] = bias[tid];
    __syncthreads();

    int ct = tid & 31, rt = tid >> 5;
    float acc[4][4];
#pragma unroll
    for (int i = 0; i < 4; i++)
#pragma unroll
        for (int j = 0; j < 4; j++) acc[i][j] = bs[ct * 4 + j];

#pragma unroll 4
    for (int k = 0; k < H; k++) {
        float4 w = *(float4*)&Ws[k * H + ct * 4];
#pragma unroll
        for (int i = 0; i < 4; i++) {
            float a = As[(rt * 4 + i) * H + k];
            acc[i][0] += a * w.x; acc[i][1] += a * w.y;
            acc[i][2] += a * w.z; acc[i][3] += a * w.w;
        }
    }
#pragma unroll
    for (int i = 0; i < 4; i++)
        *(float4*)&C[(rt * 4 + i) * H + ct * 4] =
            make_float4(acc[i][0], acc[i][1], acc[i][2], acc[i][3]);
}

// ---------------------------------------------------------------------------
// Kernel 3 (pairz): one CTA per (bm, t): build ONE 128-n A tile, one MMA
// phase (3-term bf16 split: hh + hl + lh), write z rows to g_z.
// Grid order t-major (bm fastest) so concurrent CTAs share vp tiles in L2.
// CTA-scheduler overlaps build phase of one resident CTA with MMA of the
// other — no intra-CTA pipelining needed.
// ---------------------------------------------------------------------------
#define SM_AHI  0
#define SM_ALO  34816
#define SM_BHI  69632
#define SM_BLO  88064
#define SM_ZS   106496
#define SM_LBS  107008
#define SM_B2S  107520
#define SM_W3S  107776
#define SM_TOTAL 108032

__global__ void __launch_bounds__(256, 2)
pairz_kernel(const float* __restrict__ b2, const float* __restrict__ W3)
{
    extern __shared__ __align__(1024) unsigned char smem[];
    uint32_t* Ahi = (uint32_t*)(smem + SM_AHI);
    uint32_t* Alo = (uint32_t*)(smem + SM_ALO);
    uint32_t* Bhi = (uint32_t*)(smem + SM_BHI);
    uint32_t* Blo = (uint32_t*)(smem + SM_BLO);
    float* zs  = (float*)(smem + SM_ZS);
    float* lbs = (float*)(smem + SM_LBS);
    float* b2s = (float*)(smem + SM_B2S);
    float* w3s = (float*)(smem + SM_W3S);

    int tid = threadIdx.x;
    int wid = tid >> 5, lid = tid & 31;
    int bid = blockIdx.x;
    int bm = bid & 511;          // t-major order: same-t CTAs adjacent
    int t = bid >> 9;
    int b = bm >> 6;
    int n0 = t * 128;

    // ---- stage W2 hi/lo, lb, b2, w3; init zs ----
    for (int idx = tid; idx < 4096; idx += 256) {
        int kp = idx >> 6, j = idx & 63;
        Bhi[kp * 72 + j] = g_W2hi[idx];
        Blo[kp * 72 + j] = g_W2lo[idx];
    }
    if (tid < 128) { lbs[tid] = g_lb[bm * H + tid]; zs[tid] = 0.f; }
    if (tid < 64) { b2s[tid] = b2[tid]; w3s[tid] = W3[tid]; }
    __syncthreads();

    const float* vpB = g_vp + b * NV * H;

    // ---- build A tile: relu(lb + vp), bf16 hi/lo split ----
    {
        int n = tid >> 1;
        int kb = (tid & 1) * 64;
        const float4* src = (const float4*)(vpB + (size_t)(n0 + n) * H + kb);
        uint32_t* dhi = Ahi + n * 68 + kb / 2;
        uint32_t* dlo = Alo + n * 68 + kb / 2;
#pragma unroll
        for (int i = 0; i < 16; i++) {
            float4 v = src[i];
            int k = kb + i * 4;
            float x0 = fmaxf(lbs[k + 0] + v.x, 0.f);
            float x1 = fmaxf(lbs[k + 1] + v.y, 0.f);
            float x2 = fmaxf(lbs[k + 2] + v.z, 0.f);
            float x3 = fmaxf(lbs[k + 3] + v.w, 0.f);
            __nv_bfloat16 h0, l0, h1, l1, h2, l2, h3, l3;
            bf16_split(x0, h0, l0); bf16_split(x1, h1, l1);
            bf16_split(x2, h2, l2); bf16_split(x3, h3, l3);
            *(uint2*)(dhi + i * 2) = make_uint2(pack_bf16(h0, h1), pack_bf16(h2, h3));
            *(uint2*)(dlo + i * 2) = make_uint2(pack_bf16(l0, l1), pack_bf16(l2, l3));
        }
    }
    __syncthreads();

    int g = lid >> 2, q = lid & 3;
    int wr = wid & 3;        // row group: rows wr*32 .. +32
    int wc = wid >> 2;       // col group: j    wc*32 .. +32

    // ---- warp MMA: 32n x 32j = 2 m-slabs x 4 j-tiles x 8 k16-steps ----
    float c[2][4][4];
#pragma unroll
    for (int s = 0; s < 2; s++)
#pragma unroll
        for (int jt = 0; jt < 4; jt++)
#pragma unroll
            for (int e = 0; e < 4; e++) c[s][jt][e] = 0.f;

#pragma unroll
    for (int ks = 0; ks < 8; ks++) {
        int wbase = ks * 8 + q;
        uint32_t ah[2][4], al[2][4], bh[4][2], bl[4][2];
#pragma unroll
        for (int s = 0; s < 2; s++) {
            int ro = (wr * 32 + s * 16 + g) * 68 + wbase;
            ah[s][0] = Ahi[ro];              al[s][0] = Alo[ro];
            ah[s][1] = Ahi[ro + 8 * 68];     al[s][1] = Alo[ro + 8 * 68];
            ah[s][2] = Ahi[ro + 4];          al[s][2] = Alo[ro + 4];
            ah[s][3] = Ahi[ro + 8 * 68 + 4]; al[s][3] = Alo[ro + 8 * 68 + 4];
        }
#pragma unroll
        for (int jt = 0; jt < 4; jt++) {
            int bo = wbase * 72 + wc * 32 + jt * 8 + g;
            bh[jt][0] = Bhi[bo];           bl[jt][0] = Blo[bo];
            bh[jt][1] = Bhi[bo + 4 * 72];  bl[jt][1] = Blo[bo + 4 * 72];
        }
#pragma unroll
        for (int s = 0; s < 2; s++)
#pragma unroll
            for (int jt = 0; jt < 4; jt++) {
                // 3-term split: hi*hi + hi*lo + lo*hi (lo*lo ~2^-18, dropped)
                mma_bf16(c[s][jt], ah[s], bl[jt]);
                mma_bf16(c[s][jt], al[s], bh[jt]);
                mma_bf16(c[s][jt], ah[s], bh[jt]);
            }
    }

    // ---- epilogue: relu(+b2)*w3 in regs, quad reduce, atomic zs ----
#pragma unroll
    for (int s = 0; s < 2; s++) {
        float z0 = 0.f, z1 = 0.f;
#pragma unroll
        for (int jt = 0; jt < 4; jt++) {
#pragma unroll
            for (int e = 0; e < 2; e++) {
                int j = wc * 32 + jt * 8 + q * 2 + e;
                float bb = b2s[j], ww = w3s[j];
                z0 += fmaxf(c[s][jt][e] + bb, 0.f) * ww;
                z1 += fmaxf(c[s][jt][2 + e] + bb, 0.f) * ww;
            }
        }
        z0 += __shfl_xor_sync(0xffffffffu, z0, 1);
        z0 += __shfl_xor_sync(0xffffffffu, z0, 2);
        z1 += __shfl_xor_sync(0xffffffffu, z1, 1);
        z1 += __shfl_xor_sync(0xffffffffu, z1, 2);
        if (q == 0) {
            int r = wr * 32 + s * 16 + g;
            atomicAdd(&zs[r], z0);      // 2 contenders per row (wc=0,1)
            atomicAdd(&zs[r + 8], z1);
        }
    }
    __syncthreads();

    // ---- write z rows (b3 omitted: softmax is shift-invariant) ----
    if (tid < 128)
        g_z[(size_t)bm * NV + n0 + tid] = zs[tid];
}

// ---------------------------------------------------------------------------
// Kernel 4 (softmax + coords): one CTA per bm.
// ---------------------------------------------------------------------------
__global__ void __launch_bounds__(256)
soft_kernel(const float* __restrict__ vc, const int* __restrict__ mask,
            float* __restrict__ out)
{
    __shared__ float zs[1024];
    __shared__ float red[24];

    int tid = threadIdx.x;
    int wid = tid >> 5, lid = tid & 31;
    int bm = blockIdx.x;
    int b = bm >> 6;

    // coalesced load of z row
    {
        const float4* src = (const float4*)(g_z + (size_t)bm * NV);
        float4 v = src[tid];
        *(float4*)&zs[tid * 4] = v;
    }
    __syncthreads();

    float mx = -3.4e38f;
    for (int n = tid; n < 1024; n += 256) mx = fmaxf(mx, zs[n]);
#pragma unroll
    for (int o = 16; o > 0; o >>= 1) mx = fmaxf(mx, __shfl_xor_sync(0xffffffffu, mx, o));
    if (lid == 0) red[wid] = mx;
    __syncthreads();
    mx = red[0];
#pragma unroll
    for (int j = 1; j < 8; j++) mx = fmaxf(mx, red[j]);

    float sum = 0.f;
    for (int n = tid; n < 1024; n += 256) {
        float e = expf(zs[n] - mx);
        zs[n] = e;
        sum += e;
    }
#pragma unroll
    for (int o = 16; o > 0; o >>= 1) sum += __shfl_xor_sync(0xffffffffu, sum, o);
    __syncthreads();
    if (lid == 0) red[wid] = sum;
    __syncthreads();
    sum = 0.f;
#pragma unroll
    for (int j = 0; j < 8; j++) sum += red[j];
    float inv = 1.f / sum;
    float mk = mask[bm] ? 1.f : 0.f;

    float cx = 0.f, cy = 0.f, cz = 0.f;
    const float* vcB = vc + (size_t)b * NV * 3;
    float* attn_out = out + 1536 + (size_t)bm * 1024;
    for (int n = tid; n < 1024; n += 256) {
        float a = zs[n] * inv * mk;
        attn_out[n] = a;
        cx += a * vcB[n * 3 + 0];
        cy += a * vcB[n * 3 + 1];
        cz += a * vcB[n * 3 + 2];
    }
#pragma unroll
    for (int o = 16; o > 0; o >>= 1) {
        cx += __shfl_xor_sync(0xffffffffu, cx, o);
        cy += __shfl_xor_sync(0xffffffffu, cy, o);
        cz += __shfl_xor_sync(0xffffffffu, cz, o);
    }
    __syncthreads();
    if (lid == 0) { red[wid] = cx; red[8 + wid] = cy; red[16 + wid] = cz; }
    __syncthreads();
    if (tid == 0) {
        float X = 0, Y = 0, Z = 0;
#pragma unroll
        for (int j = 0; j < 8; j++) { X += red[j]; Y += red[8 + j]; Z += red[16 + j]; }
        out[bm * 3 + 0] = X;
        out[bm * 3 + 1] = Y;
        out[bm * 3 + 2] = Z;
    }
}

// ---------------------------------------------------------------------------
extern "C" void kernel_launch(void* const* d_in, const int* in_sizes, int n_in,
                              void* d_out, int out_size)
{
    const float* virt = (const float*)d_in[0];
    const float* vcoords = (const float*)d_in[1];
    const float* lig = (const float*)d_in[2];
    const int* mask = (const int*)d_in[5];   // bool stored as int32
    const float* Wv = (const float*)d_in[6];
    const float* bv = (const float*)d_in[7];
    const float* Wl = (const float*)d_in[8];
    const float* bl = (const float*)d_in[9];
    const float* W1 = (const float*)d_in[10];
    const float* b1 = (const float*)d_in[11];
    const float* W2 = (const float*)d_in[12];
    const float* b2 = (const float*)d_in[13];
    const float* W3 = (const float*)d_in[14];
    // d_in[15] = b3: softmax shift-invariant, unused.
    float* out = (float*)d_out;

    size_t smem2 = (size_t)(H * H + 32 * H + H) * sizeof(float);
    cudaFuncSetAttribute(proj_kernel, cudaFuncAttributeMaxDynamicSharedMemorySize, (int)smem2);
    cudaFuncSetAttribute(pairz_kernel, cudaFuncAttributeMaxDynamicSharedMemorySize, SM_TOTAL);

    fold_kernel<<<dim3(129, 2), 128>>>(Wv, bv, Wl, bl, W1, b1);
    w2split_kernel<<<64, 64>>>(W2);
    proj_kernel<<<272, 256, smem2>>>(virt, lig);
    pairz_kernel<<<4096, 256, SM_TOTAL>>>(b2, W3);
    soft_kernel<<<512, 256>>>(vcoords, mask, out);
}

// round 9
// speedup vs baseline: 1.0947x; 1.0947x over previous
#include <cuda_runtime.h>
#include <cuda_bf16.h>
#include <cstdint>

#define H 128
#define NB 8
#define NV 1024
#define NM 64

// ---------------------------------------------------------------------------
// Scratch (device globals — no allocation allowed)
// ---------------------------------------------------------------------------
__device__ float g_WeffV[H * H];
__device__ float g_beffV[H];
__device__ float g_WeffL[H * H];
__device__ float g_beffL[H];
__device__ float g_vp[NB * NV * H];     // v_part (folded)  [8192,128]
__device__ float g_lb[NB * NM * H];     // l_part + b1      [512,128]
__device__ uint2 g_W2frag[2 * 8 * 8 * 32];  // W2 in MMA fragment order
__device__ float g_z[NB * NM * NV];     // pairwise logits [512,1024]

// ---------------------------------------------------------------------------
// Helpers
// ---------------------------------------------------------------------------
__device__ __forceinline__ uint32_t smem_u32(const void* p) {
    uint32_t a;
    asm("{ .reg .u64 t; cvta.to.shared.u64 t, %1; cvt.u32.u64 %0, t; }" : "=r"(a) : "l"(p));
    return a;
}
__device__ __forceinline__ uint32_t pack_bf16(__nv_bfloat16 lo_elem, __nv_bfloat16 hi_elem) {
    return (uint32_t)__bfloat16_as_ushort(lo_elem) |
           ((uint32_t)__bfloat16_as_ushort(hi_elem) << 16);
}
__device__ __forceinline__ void bf16_split(float x, __nv_bfloat16& hi, __nv_bfloat16& lo) {
    hi = __float2bfloat16(x);
    lo = __float2bfloat16(x - __bfloat162float(hi));
}
// bf16 tensor-core MMA (sm_80+ baseline): D[16x8] += A[16x16]*B[16x8], f32 accum.
__device__ __forceinline__ void mma_bf16(float c[4], const uint32_t a[4], const uint2& b) {
    asm volatile(
        "mma.sync.aligned.m16n8k16.row.col.f32.bf16.bf16.f32 "
        "{%0,%1,%2,%3}, {%4,%5,%6,%7}, {%8,%9}, {%0,%1,%2,%3};"
        : "+f"(c[0]), "+f"(c[1]), "+f"(c[2]), "+f"(c[3])
        : "r"(a[0]), "r"(a[1]), "r"(a[2]), "r"(a[3]), "r"(b.x), "r"(b.y));
}
// ldmatrix x4 (sm_75+ baseline): loads a0..a3 of a 16x16 bf16 row-major tile.
__device__ __forceinline__ void ldsm_x4(uint32_t a[4], uint32_t addr) {
    asm volatile("ldmatrix.sync.aligned.m8n8.x4.shared.b16 {%0,%1,%2,%3}, [%4];"
        : "=r"(a[0]), "=r"(a[1]), "=r"(a[2]), "=r"(a[3]) : "r"(addr));
}

// ---------------------------------------------------------------------------
// Kernel 1: fold Wv@W1[H:] and Wl@W1[:H] (+ biases) into single 128x128 mats.
// ---------------------------------------------------------------------------
__global__ void fold_kernel(const float* __restrict__ Wv, const float* __restrict__ bv,
                            const float* __restrict__ Wl, const float* __restrict__ bl,
                            const float* __restrict__ W1, const float* __restrict__ b1)
{
    int h = threadIdx.x;
    int row = blockIdx.x;      // 0..128
    int which = blockIdx.y;    // 0 = virtual, 1 = ligand
    const float* A;
    int w1off;
    if (which == 0) { A = (row < H) ? (Wv + row * H) : bv; w1off = H; }
    else            { A = (row < H) ? (Wl + row * H) : bl; w1off = 0; }
    float a0 = 0.f, a1 = 0.f, a2 = 0.f, a3 = 0.f;
#pragma unroll 8
    for (int hid = 0; hid < H; hid += 4) {
        a0 += A[hid + 0] * W1[(w1off + hid + 0) * H + h];
        a1 += A[hid + 1] * W1[(w1off + hid + 1) * H + h];
        a2 += A[hid + 2] * W1[(w1off + hid + 2) * H + h];
        a3 += A[hid + 3] * W1[(w1off + hid + 3) * H + h];
    }
    float acc = (a0 + a1) + (a2 + a3);
    if (row < H) {
        (which == 0 ? g_WeffV : g_WeffL)[row * H + h] = acc;
    } else {
        if (which == 1) acc += b1[h];
        (which == 0 ? g_beffV : g_beffL)[h] = acc;
    }
}

// ---------------------------------------------------------------------------
// Kernel 1b: W2 -> bf16 hi/lo split, stored in exact MMA fragment order:
// uint2[plane][ks][jt_global][lane] = (b0, b1) for that lane.
// b0 = W2 k-pair (8ks + lane%4), col (jt*8 + lane/4); b1 = k-pair +4.
// 4096 threads.
// ---------------------------------------------------------------------------
__global__ void w2frag_kernel(const float* __restrict__ W2)
{
    int idx = blockIdx.x * blockDim.x + threadIdx.x;   // 0..4095
    int plane = idx >> 11, ks = (idx >> 8) & 7, jtg = (idx >> 5) & 7, l = idx & 31;
    int q = l & 3, g = l >> 2;
    int j = jtg * 8 + g;
    int kp0 = ks * 8 + q, kp1 = kp0 + 4;
    float w00 = W2[(2 * kp0) * 64 + j], w01 = W2[(2 * kp0 + 1) * 64 + j];
    float w10 = W2[(2 * kp1) * 64 + j], w11 = W2[(2 * kp1 + 1) * 64 + j];
    __nv_bfloat16 h00, l00, h01, l01, h10, l10, h11, l11;
    bf16_split(w00, h00, l00); bf16_split(w01, h01, l01);
    bf16_split(w10, h10, l10); bf16_split(w11, h11, l11);
    uint2 v;
    if (plane == 0) v = make_uint2(pack_bf16(h00, h01), pack_bf16(h10, h11));
    else            v = make_uint2(pack_bf16(l00, l01), pack_bf16(l10, l11));
    g_W2frag[idx] = v;
}

// ---------------------------------------------------------------------------
// Kernel 2: projections (known-good from R2).
// ---------------------------------------------------------------------------
__global__ void proj_kernel(const float* __restrict__ virt, const float* __restrict__ lig)
{
    extern __shared__ float sm[];
    float* Ws = sm;
    float* As = Ws + H * H;
    float* bs = As + 32 * H;

    int bid = blockIdx.x;
    const float *A, *W, *bias;
    float* C;
    if (bid < 256) { A = virt + bid * 32 * H; W = g_WeffV; bias = g_beffV; C = g_vp + bid * 32 * H; }
    else { int r = bid - 256; A = lig + r * 32 * H; W = g_WeffL; bias = g_beffL; C = g_lb + r * 32 * H; }

    int tid = threadIdx.x;
    for (int i = tid; i < H * H / 4; i += 256)
        ((float4*)Ws)[i] = ((const float4*)W)[i];
    for (int i = tid; i < 32 * H / 4; i += 256)
        ((float4*)As)[i] = ((const float4*)A)[i];
    if (tid < H) bs[tid] = bias[tid];
    __syncthreads();

    int ct = tid & 31, rt = tid >> 5;
    float acc[4][4];
#pragma unroll
    for (int i = 0; i < 4; i++)
#pragma unroll
        for (int j = 0; j < 4; j++) acc[i][j] = bs[ct * 4 + j];

#pragma unroll 4
    for (int k = 0; k < H; k++) {
        float4 w = *(float4*)&Ws[k * H + ct * 4];
#pragma unroll
        for (int i = 0; i < 4; i++) {
            float a = As[(rt * 4 + i) * H + k];
            acc[i][0] += a * w.x; acc[i][1] += a * w.y;
            acc[i][2] += a * w.z; acc[i][3] += a * w.w;
        }
    }
#pragma unroll
    for (int i = 0; i < 4; i++)
        *(float4*)&C[(rt * 4 + i) * H + ct * 4] =
            make_float4(acc[i][0], acc[i][1], acc[i][2], acc[i][3]);
}

// ---------------------------------------------------------------------------
// Kernel 3 (pairz): one CTA per (bm, t). A fragments via ldmatrix.x4,
// B fragments via pre-swizzled LDS.64, term-major 3-term split MMA.
// SMEM: AHI [0,34816) ALO [34816,69632) BS [69632,102400)
//       zs 102400, lbs 102912, b2s 103424, w3s 103680, total 103936
// ---------------------------------------------------------------------------
#define SM_AHI  0
#define SM_ALO  34816
#define SM_BS   69632
#define SM_ZS   102400
#define SM_LBS  102912
#define SM_B2S  103424
#define SM_W3S  103680
#define SM_TOTAL 103936

__global__ void __launch_bounds__(256, 2)
pairz_kernel(const float* __restrict__ b2, const float* __restrict__ W3)
{
    extern __shared__ __align__(1024) unsigned char smem[];
    uint32_t* Ahi = (uint32_t*)(smem + SM_AHI);
    uint32_t* Alo = (uint32_t*)(smem + SM_ALO);
    uint2* Bs  = (uint2*)(smem + SM_BS);
    float* zs  = (float*)(smem + SM_ZS);
    float* lbs = (float*)(smem + SM_LBS);
    float* b2s = (float*)(smem + SM_B2S);
    float* w3s = (float*)(smem + SM_W3S);

    int tid = threadIdx.x;
    int wid = tid >> 5, lid = tid & 31;
    int bid = blockIdx.x;
    int bm = bid & 511;          // t-major order: same-t CTAs adjacent (L2 reuse)
    int t = bid >> 9;
    int b = bm >> 6;
    int n0 = t * 128;

    // ---- stage B fragments (straight copy), lb, b2, w3; init zs ----
    {
        const uint4* src = (const uint4*)g_W2frag;
        uint4* dst = (uint4*)Bs;
        for (int i = tid; i < 2048; i += 256) dst[i] = src[i];
    }
    if (tid < 128) { lbs[tid] = g_lb[bm * H + tid]; zs[tid] = 0.f; }
    if (tid < 64) { b2s[tid] = b2[tid]; w3s[tid] = W3[tid]; }
    __syncthreads();

    const float* vpB = g_vp + b * NV * H;

    // ---- build A tile: relu(lb + vp), bf16 hi/lo split, stride-68 rows ----
    {
        int n = tid >> 1;
        int kb = (tid & 1) * 64;
        const float4* src = (const float4*)(vpB + (size_t)(n0 + n) * H + kb);
        uint32_t* dhi = Ahi + n * 68 + kb / 2;
        uint32_t* dlo = Alo + n * 68 + kb / 2;
#pragma unroll
        for (int i = 0; i < 16; i++) {
            float4 v = src[i];
            int k = kb + i * 4;
            float x0 = fmaxf(lbs[k + 0] + v.x, 0.f);
            float x1 = fmaxf(lbs[k + 1] + v.y, 0.f);
            float x2 = fmaxf(lbs[k + 2] + v.z, 0.f);
            float x3 = fmaxf(lbs[k + 3] + v.w, 0.f);
            __nv_bfloat16 h0, l0, h1, l1, h2, l2, h3, l3;
            bf16_split(x0, h0, l0); bf16_split(x1, h1, l1);
            bf16_split(x2, h2, l2); bf16_split(x3, h3, l3);
            *(uint2*)(dhi + i * 2) = make_uint2(pack_bf16(h0, h1), pack_bf16(h2, h3));
            *(uint2*)(dlo + i * 2) = make_uint2(pack_bf16(l0, l1), pack_bf16(l2, l3));
        }
    }
    __syncthreads();

    int q = lid & 3, g = lid >> 2;
    int wr = wid & 3;        // row group: rows wr*32 .. +32
    int wc = wid >> 2;       // col group: j    wc*32 .. +32

    // ldmatrix lane pointers (bytes): row = wr*32 + s*16 + (lid&15),
    // word offset = (lid>=16 ? 4 : 0); +ks*8 words per step.
    uint32_t sb = smem_u32(smem);
    uint32_t aoff = (uint32_t)(((wr * 32 + (lid & 15)) * 68 + ((lid >> 4) << 2)) * 4);
    uint32_t aHi0 = sb + SM_AHI + aoff;
    uint32_t aHi1 = aHi0 + 16 * 68 * 4;
    uint32_t aLo0 = sb + SM_ALO + aoff;
    uint32_t aLo1 = aLo0 + 16 * 68 * 4;

    // ---- warp MMA: 32n x 32j, 8 k16-steps, term-major 3-term split ----
    float c[2][4][4];
#pragma unroll
    for (int s = 0; s < 2; s++)
#pragma unroll
        for (int jt = 0; jt < 4; jt++)
#pragma unroll
            for (int e = 0; e < 4; e++) c[s][jt][e] = 0.f;

#pragma unroll
    for (int ks = 0; ks < 8; ks++) {
        uint32_t ah[2][4], al[2][4];
        ldsm_x4(ah[0], aHi0 + ks * 32);
        ldsm_x4(ah[1], aHi1 + ks * 32);
        ldsm_x4(al[0], aLo0 + ks * 32);
        ldsm_x4(al[1], aLo1 + ks * 32);

        uint2 bh[4], bl[4];
        int bbase = (ks * 8 + wc * 4) * 32 + lid;
#pragma unroll
        for (int jt = 0; jt < 4; jt++) {
            bh[jt] = Bs[bbase + jt * 32];
            bl[jt] = Bs[2048 + bbase + jt * 32];
        }

        // term-major: 8 independent MMAs between accumulator reuses
#pragma unroll
        for (int s = 0; s < 2; s++)
#pragma unroll
            for (int jt = 0; jt < 4; jt++)
                mma_bf16(c[s][jt], ah[s], bh[jt]);
#pragma unroll
        for (int s = 0; s < 2; s++)
#pragma unroll
            for (int jt = 0; jt < 4; jt++)
                mma_bf16(c[s][jt], al[s], bh[jt]);
#pragma unroll
        for (int s = 0; s < 2; s++)
#pragma unroll
            for (int jt = 0; jt < 4; jt++)
                mma_bf16(c[s][jt], ah[s], bl[jt]);
    }

    // ---- epilogue: relu(+b2)*w3 in regs, quad reduce, atomic zs ----
#pragma unroll
    for (int s = 0; s < 2; s++) {
        float z0 = 0.f, z1 = 0.f;
#pragma unroll
        for (int jt = 0; jt < 4; jt++) {
#pragma unroll
            for (int e = 0; e < 2; e++) {
                int j = wc * 32 + jt * 8 + q * 2 + e;
                float bb = b2s[j], ww = w3s[j];
                z0 += fmaxf(c[s][jt][e] + bb, 0.f) * ww;
                z1 += fmaxf(c[s][jt][2 + e] + bb, 0.f) * ww;
            }
        }
        z0 += __shfl_xor_sync(0xffffffffu, z0, 1);
        z0 += __shfl_xor_sync(0xffffffffu, z0, 2);
        z1 += __shfl_xor_sync(0xffffffffu, z1, 1);
        z1 += __shfl_xor_sync(0xffffffffu, z1, 2);
        if (q == 0) {
            int r = wr * 32 + s * 16 + g;
            atomicAdd(&zs[r], z0);      // 2 contenders per row (wc=0,1)
            atomicAdd(&zs[r + 8], z1);
        }
    }
    __syncthreads();

    // ---- write z rows (b3 omitted: softmax shift-invariant) ----
    if (tid < 128)
        g_z[(size_t)bm * NV + n0 + tid] = zs[tid];
}

// ---------------------------------------------------------------------------
// Kernel 4 (softmax + coords): one CTA per bm.
// ---------------------------------------------------------------------------
__global__ void __launch_bounds__(256)
soft_kernel(const float* __restrict__ vc, const int* __restrict__ mask,
            float* __restrict__ out)
{
    __shared__ float zs[1024];
    __shared__ float red[24];

    int tid = threadIdx.x;
    int wid = tid >> 5, lid = tid & 31;
    int bm = blockIdx.x;
    int b = bm >> 6;

    {
        const float4* src = (const float4*)(g_z + (size_t)bm * NV);
        float4 v = src[tid];
        *(float4*)&zs[tid * 4] = v;
    }
    __syncthreads();

    float mx = -3.4e38f;
    for (int n = tid; n < 1024; n += 256) mx = fmaxf(mx, zs[n]);
#pragma unroll
    for (int o = 16; o > 0; o >>= 1) mx = fmaxf(mx, __shfl_xor_sync(0xffffffffu, mx, o));
    if (lid == 0) red[wid] = mx;
    __syncthreads();
    mx = red[0];
#pragma unroll
    for (int j = 1; j < 8; j++) mx = fmaxf(mx, red[j]);

    float sum = 0.f;
    for (int n = tid; n < 1024; n += 256) {
        float e = expf(zs[n] - mx);
        zs[n] = e;
        sum += e;
    }
#pragma unroll
    for (int o = 16; o > 0; o >>= 1) sum += __shfl_xor_sync(0xffffffffu, sum, o);
    __syncthreads();
    if (lid == 0) red[wid] = sum;
    __syncthreads();
    sum = 0.f;
#pragma unroll
    for (int j = 0; j < 8; j++) sum += red[j];
    float inv = 1.f / sum;
    float mk = mask[bm] ? 1.f : 0.f;

    float cx = 0.f, cy = 0.f, cz = 0.f;
    const float* vcB = vc + (size_t)b * NV * 3;
    float* attn_out = out + 1536 + (size_t)bm * 1024;
    for (int n = tid; n < 1024; n += 256) {
        float a = zs[n] * inv * mk;
        attn_out[n] = a;
        cx += a * vcB[n * 3 + 0];
        cy += a * vcB[n * 3 + 1];
        cz += a * vcB[n * 3 + 2];
    }
#pragma unroll
    for (int o = 16; o > 0; o >>= 1) {
        cx += __shfl_xor_sync(0xffffffffu, cx, o);
        cy += __shfl_xor_sync(0xffffffffu, cy, o);
        cz += __shfl_xor_sync(0xffffffffu, cz, o);
    }
    __syncthreads();
    if (lid == 0) { red[wid] = cx; red[8 + wid] = cy; red[16 + wid] = cz; }
    __syncthreads();
    if (tid == 0) {
        float X = 0, Y = 0, Z = 0;
#pragma unroll
        for (int j = 0; j < 8; j++) { X += red[j]; Y += red[8 + j]; Z += red[16 + j]; }
        out[bm * 3 + 0] = X;
        out[bm * 3 + 1] = Y;
        out[bm * 3 + 2] = Z;
    }
}

// ---------------------------------------------------------------------------
extern "C" void kernel_launch(void* const* d_in, const int* in_sizes, int n_in,
                              void* d_out, int out_size)
{
    const float* virt = (const float*)d_in[0];
    const float* vcoords = (const float*)d_in[1];
    const float* lig = (const float*)d_in[2];
    const int* mask = (const int*)d_in[5];   // bool stored as int32
    const float* Wv = (const float*)d_in[6];
    const float* bv = (const float*)d_in[7];
    const float* Wl = (const float*)d_in[8];
    const float* bl = (const float*)d_in[9];
    const float* W1 = (const float*)d_in[10];
    const float* b1 = (const float*)d_in[11];
    const float* W2 = (const float*)d_in[12];
    const float* b2 = (const float*)d_in[13];
    const float* W3 = (const float*)d_in[14];
    // d_in[15] = b3: softmax shift-invariant, unused.
    float* out = (float*)d_out;

    size_t smem2 = (size_t)(H * H + 32 * H + H) * sizeof(float);
    cudaFuncSetAttribute(proj_kernel, cudaFuncAttributeMaxDynamicSharedMemorySize, (int)smem2);
    cudaFuncSetAttribute(pairz_kernel, cudaFuncAttributeMaxDynamicSharedMemorySize, SM_TOTAL);

    fold_kernel<<<dim3(129, 2), 128>>>(Wv, bv, Wl, bl, W1, b1);
    w2frag_kernel<<<16, 256>>>(W2);
    proj_kernel<<<272, 256, smem2>>>(virt, lig);
    pairz_kernel<<<4096, 256, SM_TOTAL>>>(b2, W3);
    soft_kernel<<<512, 256>>>(vcoords, mask, out);
}

// round 10
// speedup vs baseline: 2.4378x; 2.2269x over previous
#include <cuda_runtime.h>
#include <cuda_bf16.h>
#include <cstdint>

#define H 128
#define NB 8
#define NV 1024
#define NM 64

// ---------------------------------------------------------------------------
// Scratch (device globals — no allocation allowed)
// ---------------------------------------------------------------------------
__device__ float g_WeffV[H * H];
__device__ float g_beffV[H];
__device__ float g_WeffL[H * H];
__device__ float g_beffL[H];
__device__ float g_vp[NB * NV * H];     // v_part (folded)  [8192,128]
__device__ float g_lb[NB * NM * H];     // l_part + b1      [512,128]
__device__ uint2 g_W2frag[2 * 8 * 8 * 32];  // W2 in MMA fragment order
__device__ float g_z[NB * NM * NV];     // pairwise logits [512,1024]

// ---------------------------------------------------------------------------
// Helpers
// ---------------------------------------------------------------------------
__device__ __forceinline__ uint32_t pack_bf16(__nv_bfloat16 lo_elem, __nv_bfloat16 hi_elem) {
    return (uint32_t)__bfloat16_as_ushort(lo_elem) |
           ((uint32_t)__bfloat16_as_ushort(hi_elem) << 16);
}
__device__ __forceinline__ void bf16_split(float x, __nv_bfloat16& hi, __nv_bfloat16& lo) {
    hi = __float2bfloat16(x);
    lo = __float2bfloat16(x - __bfloat162float(hi));
}
// bf16 tensor-core MMA (sm_80+ baseline): D[16x8] += A[16x16]*B[16x8], f32 accum.
__device__ __forceinline__ void mma_bf16(float c[4], const uint32_t a[4], const uint2& b) {
    asm volatile(
        "mma.sync.aligned.m16n8k16.row.col.f32.bf16.bf16.f32 "
        "{%0,%1,%2,%3}, {%4,%5,%6,%7}, {%8,%9}, {%0,%1,%2,%3};"
        : "+f"(c[0]), "+f"(c[1]), "+f"(c[2]), "+f"(c[3])
        : "r"(a[0]), "r"(a[1]), "r"(a[2]), "r"(a[3]), "r"(b.x), "r"(b.y));
}
// relu(v+lb) -> bf16 hi plane + bf16 residual plane, packed x2.
__device__ __forceinline__ void make_frag(float2 v, float2 lbv, uint32_t& ah, uint32_t& al) {
    float x0 = fmaxf(v.x + lbv.x, 0.f);
    float x1 = fmaxf(v.y + lbv.y, 0.f);
    uint32_t h;
    asm("cvt.rn.bf16x2.f32 %0, %1, %2;" : "=r"(h) : "f"(x1), "f"(x0));
    float h0 = __uint_as_float(h << 16);
    float h1 = __uint_as_float(h & 0xffff0000u);
    float r0 = x0 - h0, r1 = x1 - h1;
    uint32_t l;
    asm("cvt.rn.bf16x2.f32 %0, %1, %2;" : "=r"(l) : "f"(r1), "f"(r0));
    ah = h; al = l;
}

// ---------------------------------------------------------------------------
// Kernel 1: fold Wv@W1[H:] and Wl@W1[:H] (+ biases) into single 128x128 mats.
// ---------------------------------------------------------------------------
__global__ void fold_kernel(const float* __restrict__ Wv, const float* __restrict__ bv,
                            const float* __restrict__ Wl, const float* __restrict__ bl,
                            const float* __restrict__ W1, const float* __restrict__ b1)
{
    int h = threadIdx.x;
    int row = blockIdx.x;      // 0..128
    int which = blockIdx.y;    // 0 = virtual, 1 = ligand
    const float* A;
    int w1off;
    if (which == 0) { A = (row < H) ? (Wv + row * H) : bv; w1off = H; }
    else            { A = (row < H) ? (Wl + row * H) : bl; w1off = 0; }
    float a0 = 0.f, a1 = 0.f, a2 = 0.f, a3 = 0.f;
#pragma unroll 8
    for (int hid = 0; hid < H; hid += 4) {
        a0 += A[hid + 0] * W1[(w1off + hid + 0) * H + h];
        a1 += A[hid + 1] * W1[(w1off + hid + 1) * H + h];
        a2 += A[hid + 2] * W1[(w1off + hid + 2) * H + h];
        a3 += A[hid + 3] * W1[(w1off + hid + 3) * H + h];
    }
    float acc = (a0 + a1) + (a2 + a3);
    if (row < H) {
        (which == 0 ? g_WeffV : g_WeffL)[row * H + h] = acc;
    } else {
        if (which == 1) acc += b1[h];
        (which == 0 ? g_beffV : g_beffL)[h] = acc;
    }
}

// ---------------------------------------------------------------------------
// Kernel 1b: W2 -> bf16 hi/lo split in exact MMA fragment order:
// uint2[plane][ks][jt_global][lane].
// ---------------------------------------------------------------------------
__global__ void w2frag_kernel(const float* __restrict__ W2)
{
    int idx = blockIdx.x * blockDim.x + threadIdx.x;   // 0..4095
    int plane = idx >> 11, ks = (idx >> 8) & 7, jtg = (idx >> 5) & 7, l = idx & 31;
    int q = l & 3, g = l >> 2;
    int j = jtg * 8 + g;
    int kp0 = ks * 8 + q, kp1 = kp0 + 4;
    float w00 = W2[(2 * kp0) * 64 + j], w01 = W2[(2 * kp0 + 1) * 64 + j];
    float w10 = W2[(2 * kp1) * 64 + j], w11 = W2[(2 * kp1 + 1) * 64 + j];
    __nv_bfloat16 h00, l00, h01, l01, h10, l10, h11, l11;
    bf16_split(w00, h00, l00); bf16_split(w01, h01, l01);
    bf16_split(w10, h10, l10); bf16_split(w11, h11, l11);
    uint2 v;
    if (plane == 0) v = make_uint2(pack_bf16(h00, h01), pack_bf16(h10, h11));
    else            v = make_uint2(pack_bf16(l00, l01), pack_bf16(l10, l11));
    g_W2frag[idx] = v;
}

// ---------------------------------------------------------------------------
// Kernel 2: projections (known-good from R2).
// ---------------------------------------------------------------------------
__global__ void proj_kernel(const float* __restrict__ virt, const float* __restrict__ lig)
{
    extern __shared__ float sm[];
    float* Ws = sm;
    float* As = Ws + H * H;
    float* bs = As + 32 * H;

    int bid = blockIdx.x;
    const float *A, *W, *bias;
    float* C;
    if (bid < 256) { A = virt + bid * 32 * H; W = g_WeffV; bias = g_beffV; C = g_vp + bid * 32 * H; }
    else { int r = bid - 256; A = lig + r * 32 * H; W = g_WeffL; bias = g_beffL; C = g_lb + r * 32 * H; }

    int tid = threadIdx.x;
    for (int i = tid; i < H * H / 4; i += 256)
        ((float4*)Ws)[i] = ((const float4*)W)[i];
    for (int i = tid; i < 32 * H / 4; i += 256)
        ((float4*)As)[i] = ((const float4*)A)[i];
    if (tid < H) bs[tid] = bias[tid];
    __syncthreads();

    int ct = tid & 31, rt = tid >> 5;
    float acc[4][4];
#pragma unroll
    for (int i = 0; i < 4; i++)
#pragma unroll
        for (int j = 0; j < 4; j++) acc[i][j] = bs[ct * 4 + j];

#pragma unroll 4
    for (int k = 0; k < H; k++) {
        float4 w = *(float4*)&Ws[k * H + ct * 4];
#pragma unroll
        for (int i = 0; i < 4; i++) {
            float a = As[(rt * 4 + i) * H + k];
            acc[i][0] += a * w.x; acc[i][1] += a * w.y;
            acc[i][2] += a * w.z; acc[i][3] += a * w.w;
        }
    }
#pragma unroll
    for (int i = 0; i < 4; i++)
        *(float4*)&C[(rt * 4 + i) * H + ct * 4] =
            make_float4(acc[i][0], acc[i][1], acc[i][2], acc[i][3]);
}

// ---------------------------------------------------------------------------
// Kernel 3 (pairz): one CTA = 128 threads = 4 warps per (bm, t) tile.
// Warp w owns rows w*32..w*32+31 and ALL 64 j. A fragments built in
// registers straight from g_vp (float2 LDG + relu + bf16x2 split); B via
// LDG from g_W2frag (L1-resident, shared across CTAs). No smem, no
// barriers, no atomics: z complete in-warp, stored directly to g_z.
// ---------------------------------------------------------------------------
__global__ void __launch_bounds__(128, 3)
pairz_kernel(const float* __restrict__ b2, const float* __restrict__ W3)
{
    int tid = threadIdx.x;
    int wid = tid >> 5, lid = tid & 31;
    int q = lid & 3, g = lid >> 2;
    int bid = blockIdx.x;
    int bm = bid & 511;          // t-major: same-t CTAs adjacent (L1/L2 reuse)
    int t = bid >> 9;
    int b = bm >> 6;
    int n0 = t * 128;

    const float* vpB = g_vp + (size_t)b * NV * H;
    // 4 row-base pointers in float2 units; lane column offset 2q floats.
    const float2* pr0;
    {
        const float* base = vpB + (size_t)(n0 + wid * 32 + g) * H + 2 * q;
        pr0 = (const float2*)base;
    }
    const float2* lb2 = (const float2*)(g_lb + (size_t)bm * H) + q;

    float c[2][8][4];
#pragma unroll
    for (int s = 0; s < 2; s++)
#pragma unroll
        for (int jt = 0; jt < 8; jt++)
#pragma unroll
            for (int e = 0; e < 4; e++) c[s][jt][e] = 0.f;

    const uint2* Wf = g_W2frag;

#pragma unroll
    for (int ks = 0; ks < 8; ks++) {
        float2 lbl = __ldg(lb2 + ks * 8);        // cols 16ks+2q, +1
        float2 lbh = __ldg(lb2 + ks * 8 + 4);    // cols 16ks+2q+8, +9

        uint32_t ah[2][4], al[2][4];
#pragma unroll
        for (int s = 0; s < 2; s++) {
            const float2* r0 = pr0 + s * (16 * H / 2);        // row base+s*16+g
            const float2* r1 = pr0 + s * (16 * H / 2) + 8 * H / 2;  // +8 rows
            make_frag(__ldg(r0 + ks * 8),     lbl, ah[s][0], al[s][0]);
            make_frag(__ldg(r1 + ks * 8),     lbl, ah[s][1], al[s][1]);
            make_frag(__ldg(r0 + ks * 8 + 4), lbh, ah[s][2], al[s][2]);
            make_frag(__ldg(r1 + ks * 8 + 4), lbh, ah[s][3], al[s][3]);
        }

        uint2 bh[8], bl[8];
#pragma unroll
        for (int jt = 0; jt < 8; jt++) {
            bh[jt] = __ldg(Wf + ks * 256 + jt * 32 + lid);
            bl[jt] = __ldg(Wf + 2048 + ks * 256 + jt * 32 + lid);
        }

        // term-major 3-term split: 16 independent MMAs per term
#pragma unroll
        for (int s = 0; s < 2; s++)
#pragma unroll
            for (int jt = 0; jt < 8; jt++)
                mma_bf16(c[s][jt], ah[s], bh[jt]);
#pragma unroll
        for (int s = 0; s < 2; s++)
#pragma unroll
            for (int jt = 0; jt < 8; jt++)
                mma_bf16(c[s][jt], al[s], bh[jt]);
#pragma unroll
        for (int s = 0; s < 2; s++)
#pragma unroll
            for (int jt = 0; jt < 8; jt++)
                mma_bf16(c[s][jt], ah[s], bl[jt]);
    }

    // ---- epilogue: z = w3 . relu(c + b2); full sum in-warp, no atomics ----
    float* zrow = g_z + (size_t)bm * NV + n0 + wid * 32;
#pragma unroll
    for (int s = 0; s < 2; s++) {
        float z0 = 0.f, z1 = 0.f;
#pragma unroll
        for (int jt = 0; jt < 8; jt++) {
#pragma unroll
            for (int e = 0; e < 2; e++) {
                int j = jt * 8 + 2 * q + e;
                float bb = __ldg(b2 + j), ww = __ldg(W3 + j);
                z0 += fmaxf(c[s][jt][e] + bb, 0.f) * ww;
                z1 += fmaxf(c[s][jt][2 + e] + bb, 0.f) * ww;
            }
        }
        z0 += __shfl_xor_sync(0xffffffffu, z0, 1);
        z0 += __shfl_xor_sync(0xffffffffu, z0, 2);
        z1 += __shfl_xor_sync(0xffffffffu, z1, 1);
        z1 += __shfl_xor_sync(0xffffffffu, z1, 2);
        if (q == 0) {
            zrow[s * 16 + g] = z0;
            zrow[s * 16 + g + 8] = z1;
        }
    }
}

// ---------------------------------------------------------------------------
// Kernel 4 (softmax + coords): one CTA per bm.
// ---------------------------------------------------------------------------
__global__ void __launch_bounds__(256)
soft_kernel(const float* __restrict__ vc, const int* __restrict__ mask,
            float* __restrict__ out)
{
    __shared__ float zs[1024];
    __shared__ float red[24];

    int tid = threadIdx.x;
    int wid = tid >> 5, lid = tid & 31;
    int bm = blockIdx.x;
    int b = bm >> 6;

    {
        const float4* src = (const float4*)(g_z + (size_t)bm * NV);
        float4 v = src[tid];
        *(float4*)&zs[tid * 4] = v;
    }
    __syncthreads();

    float mx = -3.4e38f;
    for (int n = tid; n < 1024; n += 256) mx = fmaxf(mx, zs[n]);
#pragma unroll
    for (int o = 16; o > 0; o >>= 1) mx = fmaxf(mx, __shfl_xor_sync(0xffffffffu, mx, o));
    if (lid == 0) red[wid] = mx;
    __syncthreads();
    mx = red[0];
#pragma unroll
    for (int j = 1; j < 8; j++) mx = fmaxf(mx, red[j]);

    float sum = 0.f;
    for (int n = tid; n < 1024; n += 256) {
        float e = expf(zs[n] - mx);
        zs[n] = e;
        sum += e;
    }
#pragma unroll
    for (int o = 16; o > 0; o >>= 1) sum += __shfl_xor_sync(0xffffffffu, sum, o);
    __syncthreads();
    if (lid == 0) red[wid] = sum;
    __syncthreads();
    sum = 0.f;
#pragma unroll
    for (int j = 0; j < 8; j++) sum += red[j];
    float inv = 1.f / sum;
    float mk = mask[bm] ? 1.f : 0.f;

    float cx = 0.f, cy = 0.f, cz = 0.f;
    const float* vcB = vc + (size_t)b * NV * 3;
    float* attn_out = out + 1536 + (size_t)bm * 1024;
    for (int n = tid; n < 1024; n += 256) {
        float a = zs[n] * inv * mk;
        attn_out[n] = a;
        cx += a * vcB[n * 3 + 0];
        cy += a * vcB[n * 3 + 1];
        cz += a * vcB[n * 3 + 2];
    }
#pragma unroll
    for (int o = 16; o > 0; o >>= 1) {
        cx += __shfl_xor_sync(0xffffffffu, cx, o);
        cy += __shfl_xor_sync(0xffffffffu, cy, o);
        cz += __shfl_xor_sync(0xffffffffu, cz, o);
    }
    __syncthreads();
    if (lid == 0) { red[wid] = cx; red[8 + wid] = cy; red[16 + wid] = cz; }
    __syncthreads();
    if (tid == 0) {
        float X = 0, Y = 0, Z = 0;
#pragma unroll
        for (int j = 0; j < 8; j++) { X += red[j]; Y += red[8 + j]; Z += red[16 + j]; }
        out[bm * 3 + 0] = X;
        out[bm * 3 + 1] = Y;
        out[bm * 3 + 2] = Z;
    }
}

// ---------------------------------------------------------------------------
extern "C" void kernel_launch(void* const* d_in, const int* in_sizes, int n_in,
                              void* d_out, int out_size)
{
    const float* virt = (const float*)d_in[0];
    const float* vcoords = (const float*)d_in[1];
    const float* lig = (const float*)d_in[2];
    const int* mask = (const int*)d_in[5];   // bool stored as int32
    const float* Wv = (const float*)d_in[6];
    const float* bv = (const float*)d_in[7];
    const float* Wl = (const float*)d_in[8];
    const float* bl = (const float*)d_in[9];
    const float* W1 = (const float*)d_in[10];
    const float* b1 = (const float*)d_in[11];
    const float* W2 = (const float*)d_in[12];
    const float* b2 = (const float*)d_in[13];
    const float* W3 = (const float*)d_in[14];
    // d_in[15] = b3: softmax shift-invariant, unused.
    float* out = (float*)d_out;

    size_t smem2 = (size_t)(H * H + 32 * H + H) * sizeof(float);
    cudaFuncSetAttribute(proj_kernel, cudaFuncAttributeMaxDynamicSharedMemorySize, (int)smem2);

    fold_kernel<<<dim3(129, 2), 128>>>(Wv, bv, Wl, bl, W1, b1);
    w2frag_kernel<<<16, 256>>>(W2);
    proj_kernel<<<272, 256, smem2>>>(virt, lig);
    pairz_kernel<<<4096, 128>>>(b2, W3);
    soft_kernel<<<512, 256>>>(vcoords, mask, out);
}

// round 12
// speedup vs baseline: 2.4897x; 1.0213x over previous
#include <cuda_runtime.h>
#include <cuda_bf16.h>
#include <cstdint>

#define H 128
#define NB 8
#define NV 1024
#define NM 64

// ---------------------------------------------------------------------------
// Scratch (device globals — no allocation allowed)
// ---------------------------------------------------------------------------
__device__ float g_WeffV[H * H];
__device__ float g_beffV[H];
__device__ float g_WeffL[H * H];
__device__ float g_beffL[H];
__device__ float g_vp[NB * NV * H];     // v_part (folded)  [8192,128]
__device__ float g_lb[NB * NM * H];     // l_part + b1      [512,128]
// W2 fragments, k-PERMUTED layout: uint4[ks][jt][lane] = (bh0,bh1,bl0,bl1)
// slot b0 = phys k {16ks+4q, +1}, slot b1 = phys k {16ks+4q+2, +3}, col jt*8+g
__device__ uint4 g_W2f4[8 * 8 * 32];
__device__ float g_z[NB * NM * NV];     // pairwise logits [512,1024]

// ---------------------------------------------------------------------------
// Helpers
// ---------------------------------------------------------------------------
__device__ __forceinline__ uint32_t pack_bf16(__nv_bfloat16 lo_elem, __nv_bfloat16 hi_elem) {
    return (uint32_t)__bfloat16_as_ushort(lo_elem) |
           ((uint32_t)__bfloat16_as_ushort(hi_elem) << 16);
}
__device__ __forceinline__ void bf16_split(float x, __nv_bfloat16& hi, __nv_bfloat16& lo) {
    hi = __float2bfloat16(x);
    lo = __float2bfloat16(x - __bfloat162float(hi));
}
// bf16 tensor-core MMA (sm_80+ baseline): D[16x8] += A[16x16]*B[16x8], f32 accum.
__device__ __forceinline__ void mma_bf16(float c[4], const uint32_t a[4], const uint2& b) {
    asm volatile(
        "mma.sync.aligned.m16n8k16.row.col.f32.bf16.bf16.f32 "
        "{%0,%1,%2,%3}, {%4,%5,%6,%7}, {%8,%9}, {%0,%1,%2,%3};"
        : "+f"(c[0]), "+f"(c[1]), "+f"(c[2]), "+f"(c[3])
        : "r"(a[0]), "r"(a[1]), "r"(a[2]), "r"(a[3]), "r"(b.x), "r"(b.y));
}
// relu(v+lb) over 2 cols -> packed bf16 hi + residual lo.
__device__ __forceinline__ void make_frag2(float vx, float vy, float lx, float ly,
                                           uint32_t& ah, uint32_t& al) {
    float x0 = fmaxf(vx + lx, 0.f);
    float x1 = fmaxf(vy + ly, 0.f);
    uint32_t h;
    asm("cvt.rn.bf16x2.f32 %0, %1, %2;" : "=r"(h) : "f"(x1), "f"(x0));
    float h0 = __uint_as_float(h << 16);
    float h1 = __uint_as_float(h & 0xffff0000u);
    float r0 = x0 - h0, r1 = x1 - h1;
    uint32_t l;
    asm("cvt.rn.bf16x2.f32 %0, %1, %2;" : "=r"(l) : "f"(r1), "f"(r0));
    ah = h; al = l;
}

// ---------------------------------------------------------------------------
// Kernel 1: fold Wv@W1[H:] and Wl@W1[:H] (+ biases) into single 128x128 mats.
// ---------------------------------------------------------------------------
__global__ void fold_kernel(const float* __restrict__ Wv, const float* __restrict__ bv,
                            const float* __restrict__ Wl, const float* __restrict__ bl,
                            const float* __restrict__ W1, const float* __restrict__ b1)
{
    int h = threadIdx.x;
    int row = blockIdx.x;      // 0..128
    int which = blockIdx.y;    // 0 = virtual, 1 = ligand
    const float* A;
    int w1off;
    if (which == 0) { A = (row < H) ? (Wv + row * H) : bv; w1off = H; }
    else            { A = (row < H) ? (Wl + row * H) : bl; w1off = 0; }
    float a0 = 0.f, a1 = 0.f, a2 = 0.f, a3 = 0.f;
#pragma unroll 8
    for (int hid = 0; hid < H; hid += 4) {
        a0 += A[hid + 0] * W1[(w1off + hid + 0) * H + h];
        a1 += A[hid + 1] * W1[(w1off + hid + 1) * H + h];
        a2 += A[hid + 2] * W1[(w1off + hid + 2) * H + h];
        a3 += A[hid + 3] * W1[(w1off + hid + 3) * H + h];
    }
    float acc = (a0 + a1) + (a2 + a3);
    if (row < H) {
        (which == 0 ? g_WeffV : g_WeffL)[row * H + h] = acc;
    } else {
        if (which == 1) acc += b1[h];
        (which == 0 ? g_beffV : g_beffL)[h] = acc;
    }
}

// ---------------------------------------------------------------------------
// Kernel 1b: W2 -> bf16 hi/lo fragments, k-permuted order matching the A-side
// float4 loads: b0 = phys k {16ks+4q,+1}, b1 = {16ks+4q+2,+3}.
// 2048 threads: idx = [ks][jt][lane].
// ---------------------------------------------------------------------------
__global__ void w2frag_kernel(const float* __restrict__ W2)
{
    int idx = blockIdx.x * blockDim.x + threadIdx.x;   // 0..2047
    int ks = (idx >> 8) & 7, jt = (idx >> 5) & 7, l = idx & 31;
    int q = l & 3, g = l >> 2;
    int j = jt * 8 + g;
    int k0 = ks * 16 + 4 * q;
    float w0 = W2[(k0 + 0) * 64 + j];
    float w1 = W2[(k0 + 1) * 64 + j];
    float w2 = W2[(k0 + 2) * 64 + j];
    float w3 = W2[(k0 + 3) * 64 + j];
    __nv_bfloat16 h0, l0, h1, l1, h2, l2, h3, l3;
    bf16_split(w0, h0, l0); bf16_split(w1, h1, l1);
    bf16_split(w2, h2, l2); bf16_split(w3, h3, l3);
    g_W2f4[idx] = make_uint4(pack_bf16(h0, h1), pack_bf16(h2, h3),
                             pack_bf16(l0, l1), pack_bf16(l2, l3));
}

// ---------------------------------------------------------------------------
// Kernel 2: projections (known-good from R2).
// ---------------------------------------------------------------------------
__global__ void proj_kernel(const float* __restrict__ virt, const float* __restrict__ lig)
{
    extern __shared__ float sm[];
    float* Ws = sm;
    float* As = Ws + H * H;
    float* bs = As + 32 * H;

    int bid = blockIdx.x;
    const float *A, *W, *bias;
    float* C;
    if (bid < 256) { A = virt + bid * 32 * H; W = g_WeffV; bias = g_beffV; C = g_vp + bid * 32 * H; }
    else { int r = bid - 256; A = lig + r * 32 * H; W = g_WeffL; bias = g_beffL; C = g_lb + r * 32 * H; }

    int tid = threadIdx.x;
    for (int i = tid; i < H * H / 4; i += 256)
        ((float4*)Ws)[i] = ((const float4*)W)[i];
    for (int i = tid; i < 32 * H / 4; i += 256)
        ((float4*)As)[i] = ((const float4*)A)[i];
    if (tid < H) bs[tid] = bias[tid];
    __syncthreads();

    int ct = tid & 31, rt = tid >> 5;
    float acc[4][4];
#pragma unroll
    for (int i = 0; i < 4; i++)
#pragma unroll
        for (int j = 0; j < 4; j++) acc[i][j] = bs[ct * 4 + j];

#pragma unroll 4
    for (int k = 0; k < H; k++) {
        float4 w = *(float4*)&Ws[k * H + ct * 4];
#pragma unroll
        for (int i = 0; i < 4; i++) {
            float a = As[(rt * 4 + i) * H + k];
            acc[i][0] += a * w.x; acc[i][1] += a * w.y;
            acc[i][2] += a * w.z; acc[i][3] += a * w.w;
        }
    }
#pragma unroll
    for (int i = 0; i < 4; i++)
        *(float4*)&C[(rt * 4 + i) * H + ct * 4] =
            make_float4(acc[i][0], acc[i][1], acc[i][2], acc[i][3]);
}

// ---------------------------------------------------------------------------
// Kernel 3 (pairz): one CTA = 128 threads = 4 warps per (bm, t) tile.
// Warp w owns rows w*32..+31 and all 64 j. A fragments built in registers
// from ONE LDG.128 per row-quad per ks (k-permuted slots), B via uint4 LDG
// from g_W2f4 (L1-resident). No smem, no barriers, no atomics.
// ---------------------------------------------------------------------------
__global__ void __launch_bounds__(128, 3)
pairz_kernel(const float* __restrict__ b2, const float* __restrict__ W3)
{
    int tid = threadIdx.x;
    int wid = tid >> 5, lid = tid & 31;
    int q = lid & 3, g = lid >> 2;
    int bid = blockIdx.x;
    int bm = bid & 511;          // t-major: same-t CTAs adjacent (L1/L2 reuse)
    int t = bid >> 9;
    int b = bm >> 6;
    int n0 = t * 128;

    // row base in float4 units: row = n0 + wid*32 + g, lane col offset q f4s
    const float4* pr0 = (const float4*)(g_vp + (size_t)b * NV * H) +
                        (size_t)(n0 + wid * 32 + g) * (H / 4) + q;
    const float4* lb4 = (const float4*)(g_lb + (size_t)bm * H) + q;

    float c[2][8][4];
#pragma unroll
    for (int s = 0; s < 2; s++)
#pragma unroll
        for (int jt = 0; jt < 8; jt++)
#pragma unroll
            for (int e = 0; e < 4; e++) c[s][jt][e] = 0.f;

#pragma unroll
    for (int ks = 0; ks < 8; ks++) {
        float4 lbv = __ldg(lb4 + ks * 4);   // phys cols 16ks+4q .. +3

        // A fragments: slots a0/a2 <- row g float4; a1/a3 <- row g+8 float4
        uint32_t ah[2][4], al[2][4];
#pragma unroll
        for (int s = 0; s < 2; s++) {
            float4 f0 = __ldg(pr0 + s * 16 * (H / 4) + ks * 4);
            float4 f1 = __ldg(pr0 + (s * 16 + 8) * (H / 4) + ks * 4);
            make_frag2(f0.x, f0.y, lbv.x, lbv.y, ah[s][0], al[s][0]);
            make_frag2(f0.z, f0.w, lbv.z, lbv.w, ah[s][2], al[s][2]);
            make_frag2(f1.x, f1.y, lbv.x, lbv.y, ah[s][1], al[s][1]);
            make_frag2(f1.z, f1.w, lbv.z, lbv.w, ah[s][3], al[s][3]);
        }

        uint2 bh[8], bl[8];
#pragma unroll
        for (int jt = 0; jt < 8; jt++) {
            uint4 w = __ldg(g_W2f4 + ks * 256 + jt * 32 + lid);
            bh[jt] = make_uint2(w.x, w.y);
            bl[jt] = make_uint2(w.z, w.w);
        }

        // term-major 3-term split: 16 independent MMAs per term
#pragma unroll
        for (int s = 0; s < 2; s++)
#pragma unroll
            for (int jt = 0; jt < 8; jt++)
                mma_bf16(c[s][jt], ah[s], bh[jt]);
#pragma unroll
        for (int s = 0; s < 2; s++)
#pragma unroll
            for (int jt = 0; jt < 8; jt++)
                mma_bf16(c[s][jt], al[s], bh[jt]);
#pragma unroll
        for (int s = 0; s < 2; s++)
#pragma unroll
            for (int jt = 0; jt < 8; jt++)
                mma_bf16(c[s][jt], ah[s], bl[jt]);
    }

    // ---- epilogue: z = w3 . relu(c + b2); full sum in-warp, no atomics ----
    float* zrow = g_z + (size_t)bm * NV + n0 + wid * 32;
#pragma unroll
    for (int s = 0; s < 2; s++) {
        float z0 = 0.f, z1 = 0.f;
#pragma unroll
        for (int jt = 0; jt < 8; jt++) {
#pragma unroll
            for (int e = 0; e < 2; e++) {
                int j = jt * 8 + 2 * q + e;
                float bb = __ldg(b2 + j), ww = __ldg(W3 + j);
                z0 += fmaxf(c[s][jt][e] + bb, 0.f) * ww;
                z1 += fmaxf(c[s][jt][2 + e] + bb, 0.f) * ww;
            }
        }
        z0 += __shfl_xor_sync(0xffffffffu, z0, 1);
        z0 += __shfl_xor_sync(0xffffffffu, z0, 2);
        z1 += __shfl_xor_sync(0xffffffffu, z1, 1);
        z1 += __shfl_xor_sync(0xffffffffu, z1, 2);
        if (q == 0) {
            zrow[s * 16 + g] = z0;
            zrow[s * 16 + g + 8] = z1;
        }
    }
}

// ---------------------------------------------------------------------------
// Kernel 4 (softmax + coords): one CTA per bm.
// ---------------------------------------------------------------------------
__global__ void __launch_bounds__(256)
soft_kernel(const float* __restrict__ vc, const int* __restrict__ mask,
            float* __restrict__ out)
{
    __shared__ float zs[1024];
    __shared__ float red[24];

    int tid = threadIdx.x;
    int wid = tid >> 5, lid = tid & 31;
    int bm = blockIdx.x;
    int b = bm >> 6;

    {
        const float4* src = (const float4*)(g_z + (size_t)bm * NV);
        float4 v = src[tid];
        *(float4*)&zs[tid * 4] = v;
    }
    __syncthreads();

    float mx = -3.4e38f;
    for (int n = tid; n < 1024; n += 256) mx = fmaxf(mx, zs[n]);
#pragma unroll
    for (int o = 16; o > 0; o >>= 1) mx = fmaxf(mx, __shfl_xor_sync(0xffffffffu, mx, o));
    if (lid == 0) red[wid] = mx;
    __syncthreads();
    mx = red[0];
#pragma unroll
    for (int j = 1; j < 8; j++) mx = fmaxf(mx, red[j]);

    float sum = 0.f;
    for (int n = tid; n < 1024; n += 256) {
        float e = expf(zs[n] - mx);
        zs[n] = e;
        sum += e;
    }
#pragma unroll
    for (int o = 16; o > 0; o >>= 1) sum += __shfl_xor_sync(0xffffffffu, sum, o);
    __syncthreads();
    if (lid == 0) red[wid] = sum;
    __syncthreads();
    sum = 0.f;
#pragma unroll
    for (int j = 0; j < 8; j++) sum += red[j];
    float inv = 1.f / sum;
    float mk = mask[bm] ? 1.f : 0.f;

    float cx = 0.f, cy = 0.f, cz = 0.f;
    const float* vcB = vc + (size_t)b * NV * 3;
    float* attn_out = out + 1536 + (size_t)bm * 1024;
    for (int n = tid; n < 1024; n += 256) {
        float a = zs[n] * inv * mk;
        attn_out[n] = a;
        cx += a * vcB[n * 3 + 0];
        cy += a * vcB[n * 3 + 1];
        cz += a * vcB[n * 3 + 2];
    }
#pragma unroll
    for (int o = 16; o > 0; o >>= 1) {
        cx += __shfl_xor_sync(0xffffffffu, cx, o);
        cy += __shfl_xor_sync(0xffffffffu, cy, o);
        cz += __shfl_xor_sync(0xffffffffu, cz, o);
    }
    __syncthreads();
    if (lid == 0) { red[wid] = cx; red[8 + wid] = cy; red[16 + wid] = cz; }
    __syncthreads();
    if (tid == 0) {
        float X = 0, Y = 0, Z = 0;
#pragma unroll
        for (int j = 0; j < 8; j++) { X += red[j]; Y += red[8 + j]; Z += red[16 + j]; }
        out[bm * 3 + 0] = X;
        out[bm * 3 + 1] = Y;
        out[bm * 3 + 2] = Z;
    }
}

// ---------------------------------------------------------------------------
extern "C" void kernel_launch(void* const* d_in, const int* in_sizes, int n_in,
                              void* d_out, int out_size)
{
    const float* virt = (const float*)d_in[0];
    const float* vcoords = (const float*)d_in[1];
    const float* lig = (const float*)d_in[2];
    const int* mask = (const int*)d_in[5];   // bool stored as int32
    const float* Wv = (const float*)d_in[6];
    const float* bv = (const float*)d_in[7];
    const float* Wl = (const float*)d_in[8];
    const float* bl = (const float*)d_in[9];
    const float* W1 = (const float*)d_in[10];
    const float* b1 = (const float*)d_in[11];
    const float* W2 = (const float*)d_in[12];
    const float* b2 = (const float*)d_in[13];
    const float* W3 = (const float*)d_in[14];
    // d_in[15] = b3: softmax shift-invariant, unused.
    float* out = (float*)d_out;

    size_t smem2 = (size_t)(H * H + 32 * H + H) * sizeof(float);
    cudaFuncSetAttribute(proj_kernel, cudaFuncAttributeMaxDynamicSharedMemorySize, (int)smem2);

    fold_kernel<<<dim3(129, 2), 128>>>(Wv, bv, Wl, bl, W1, b1);
    w2frag_kernel<<<8, 256>>>(W2);
    proj_kernel<<<272, 256, smem2>>>(virt, lig);
    pairz_kernel<<<4096, 128>>>(b2, W3);
    soft_kernel<<<512, 256>>>(vcoords, mask, out);
}